// round 5
// baseline (speedup 1.0000x reference)
#include <cuda_runtime.h>
#include <cuda_bf16.h>
#include <stdint.h>
#include <math.h>

#define B_DIM 8
#define Q_DIM 64
#define N_DIM 8192
#define K_DIM 512
#define C_DIM 256

#define VQ_GRID 296            // persistent vq CTAs (2 per SM)
#define N_TILES 1024           // (B*N)/64 tiles of 64 n-columns
#define REC_BLOCKS 256
#define TOTAL_BLOCKS (VQ_GRID + REC_BLOCKS)   // 552 arrivals
#define NP (N_TILES + REC_BLOCKS)             // 1280 partial slots

__device__ float g_partials[NP];
__device__ int   g_arrived;    // zero-init; reset by the finishing block
__device__ int   g_tile;       // work-stealing cursor; reset by finishing block

// ---------------- smem layout (bytes) ----------------
// rows padded to 144B (= 9 x 16B): conflict-free ldmatrix, 16B-aligned
#define EPAD 144
#define SM_RED  0                      // 16B  (4 floats)
#define SM_Z2   16                     // 512B (two half-sums per column)
#define SM_E2   528                    // 2048B (||emb_k||^2)
#define SM_ZET  2576                   // 64 * 144 = 9216B  (zeT[n][q] bf16)
#define SM_EMB  11792                  // 512 * 144 = 73728B (emb[k][q] bf16)
#define SMEM_TOTAL 85520

// ---------------- helpers ----------------
__device__ __forceinline__ uint32_t smem_u32(const void* p) {
    uint32_t a;
    asm("{ .reg .u64 t; cvta.to.shared.u64 t, %1; cvt.u32.u64 %0, t; }" : "=r"(a) : "l"(p));
    return a;
}

#define LDSM_X4(r0, r1, r2, r3, addr) \
    asm volatile("ldmatrix.sync.aligned.m8n8.x4.shared.b16 {%0,%1,%2,%3}, [%4];" \
                 : "=r"(r0), "=r"(r1), "=r"(r2), "=r"(r3) : "r"(addr))

#define MMA_BF16(a0, a1, a2, a3, b0, b1, c0, c1, c2, c3) \
    asm volatile("mma.sync.aligned.m16n8k16.row.col.f32.bf16.bf16.f32 " \
                 "{%0,%1,%2,%3}, {%4,%5,%6,%7}, {%8,%9}, {%0,%1,%2,%3};" \
                 : "+f"(c0), "+f"(c1), "+f"(c2), "+f"(c3) \
                 : "r"(a0), "r"(a1), "r"(a2), "r"(a3), "r"(b0), "r"(b1))

__device__ __forceinline__ float block_sum(float v, float* red, int nwarps) {
    #pragma unroll
    for (int off = 16; off > 0; off >>= 1)
        v += __shfl_down_sync(0xFFFFFFFFu, v, off);
    int lane = threadIdx.x & 31;
    int wid  = threadIdx.x >> 5;
    if (lane == 0) red[wid] = v;
    __syncthreads();
    if (wid == 0) {
        v = (lane < nwarps) ? red[lane] : 0.0f;
        #pragma unroll
        for (int off = 16; off > 0; off >>= 1)
            v += __shfl_down_sync(0xFFFFFFFFu, v, off);
    }
    return v;  // valid in thread 0
}

// Last-arriving block (across BOTH kernels) sums all partials in a FIXED
// order (first 128 threads, fixed stride + fixed tree) -> bit-deterministic.
__device__ __forceinline__ void finalize(float* out) {
    __shared__ float fr[4];
    __shared__ int last;
    __threadfence();
    if (threadIdx.x == 0)
        last = (atomicAdd(&g_arrived, 1) == TOTAL_BLOCKS - 1);
    __syncthreads();
    if (!last) return;
    __threadfence();
    float s = 0.0f;
    if (threadIdx.x < 128) {
        for (int i = threadIdx.x; i < NP; i += 128)
            s += g_partials[i];
    }
    #pragma unroll
    for (int off = 16; off > 0; off >>= 1)
        s += __shfl_down_sync(0xFFFFFFFFu, s, off);
    if (threadIdx.x < 128 && (threadIdx.x & 31) == 0)
        fr[threadIdx.x >> 5] = s;
    __syncthreads();
    if (threadIdx.x == 0) {
        out[0] = ((fr[0] + fr[1]) + (fr[2] + fr[3]));
        g_arrived = 0;   // reset for next graph replay
        g_tile = 0;
    }
}

// -------------------- VQ: emb prep + distance GEMM (HMMA bf16) --------------------
__global__ __launch_bounds__(128) void vq_gemm(const float* __restrict__ ze,
                                               const float* __restrict__ emb,
                                               float* __restrict__ out) {
    extern __shared__ char smem[];
    __shared__ int tile_sh;
    const uint32_t sb = smem_u32(smem);
    const int tid  = threadIdx.x;
    const int lane = tid & 31;
    const int wid  = tid >> 5;

    float* red = (float*)(smem + SM_RED);
    float* z2s = (float*)(smem + SM_Z2);

    // ---- one-time: emb fp32 (gmem, L2-hot) -> bf16 padded smem + ||emb||^2 ----
    {
        float* e2 = (float*)(smem + SM_E2);
        #pragma unroll
        for (int i = 0; i < K_DIM / 128; i++) {
            int k = tid + 128 * i;                     // stride-128 rows
            const float4* src = (const float4*)(emb + (size_t)k * Q_DIM);
            char* dst = smem + SM_EMB + k * EPAD;
            float s = 0.0f;
            #pragma unroll
            for (int j = 0; j < 16; j++) {
                float4 v = src[j];
                s = fmaf(v.x, v.x, s); s = fmaf(v.y, v.y, s);
                s = fmaf(v.z, v.z, s); s = fmaf(v.w, v.w, s);
                __nv_bfloat162 p0 = __floats2bfloat162_rn(v.x, v.y);
                __nv_bfloat162 p1 = __floats2bfloat162_rn(v.z, v.w);
                uint2 u;
                u.x = *(uint32_t*)&p0;
                u.y = *(uint32_t*)&p1;
                *(uint2*)(dst + j * 8) = u;
            }
            e2[k] = s;
        }
    }

    const float* e2s = (const float*)(smem + SM_E2);

    for (;;) {
        if (tid == 0) tile_sh = atomicAdd(&g_tile, 1);
        __syncthreads();                 // tile_sh ready + smem reuse guard
        const int tile = tile_sh;
        if (tile >= N_TILES) break;

        const int b  = tile >> 7;
        const int n0 = (tile & 127) << 6;
        const float* zp = ze + (size_t)b * Q_DIM * N_DIM + n0;

        // ---- load ze tile, transpose to zeT[n][q] bf16, exact fp32 ze2 ----
        {
            const int c  = tid & 63;    // column n within tile
            const int qh = tid >> 6;    // q parity (0/1)
            float z2 = 0.0f;
            #pragma unroll
            for (int i = 0; i < 32; i++) {
                int q = 2 * i + qh;
                float v = zp[(size_t)q * N_DIM + c];
                z2 = fmaf(v, v, z2);
                *(__nv_bfloat16*)(smem + SM_ZET + c * EPAD + q * 2) = __float2bfloat16_rn(v);
            }
            z2s[qh * 64 + c] = z2;      // ze2[c] = z2s[c] + z2s[64+c]
        }
        __syncthreads();

        // ---- A fragments: zeT rows [16*wid, 16*wid+16), all 4 k-steps ----
        uint32_t a[4][4];
        {
            uint32_t abase = sb + SM_ZET + (uint32_t)(16 * wid + (lane & 15)) * EPAD
                           + (uint32_t)(lane >> 4) * 16u;
            #pragma unroll
            for (int ks = 0; ks < 4; ks++)
                LDSM_X4(a[ks][0], a[ks][1], a[ks][2], a[ks][3], abase + ks * 32u);
        }

        float vmin0 = 3.4e38f, vmin1 = 3.4e38f;
        const uint32_t bbase = sb + SM_EMB + (uint32_t)(lane & 7) * EPAD
                             + (uint32_t)(lane >> 3) * 16u;

        #pragma unroll 2
        for (int ct = 0; ct < 64; ct++) {     // 8 codewords per iteration
            float c0 = 0.f, c1 = 0.f, c2 = 0.f, c3 = 0.f;
            #pragma unroll
            for (int kp = 0; kp < 2; kp++) {  // k-pairs: 32 q per x4 load
                uint32_t b0, b1, b2, b3;
                LDSM_X4(b0, b1, b2, b3, bbase + (uint32_t)ct * (8u * EPAD) + kp * 64u);
                MMA_BF16(a[2 * kp][0],     a[2 * kp][1],     a[2 * kp][2],     a[2 * kp][3],     b0, b1, c0, c1, c2, c3);
                MMA_BF16(a[2 * kp + 1][0], a[2 * kp + 1][1], a[2 * kp + 1][2], a[2 * kp + 1][3], b2, b3, c0, c1, c2, c3);
            }
            float2 e2 = *(const float2*)(e2s + ct * 8 + 2 * (lane & 3));
            vmin0 = fminf(vmin0, fminf(fmaf(-2.0f, c0, e2.x), fmaf(-2.0f, c1, e2.y)));
            vmin1 = fminf(vmin1, fminf(fmaf(-2.0f, c2, e2.x), fmaf(-2.0f, c3, e2.y)));
        }

        // min across the 4 lanes of each row-quad
        vmin0 = fminf(vmin0, __shfl_xor_sync(0xFFFFFFFFu, vmin0, 1));
        vmin0 = fminf(vmin0, __shfl_xor_sync(0xFFFFFFFFu, vmin0, 2));
        vmin1 = fminf(vmin1, __shfl_xor_sync(0xFFFFFFFFu, vmin1, 1));
        vmin1 = fminf(vmin1, __shfl_xor_sync(0xFFFFFFFFu, vmin1, 2));

        float part = 0.0f;
        if ((lane & 3) == 0) {
            int r0 = 16 * wid + (lane >> 2);       // n rows r0 and r0+8
            float ze2a = z2s[r0] + z2s[64 + r0];
            float ze2b = z2s[r0 + 8] + z2s[64 + r0 + 8];
            part = 1.25f * (vmin0 + ze2a) + 1.25f * (vmin1 + ze2b);
        }
        float s = block_sum(part, red, 4);
        if (tid == 0) g_partials[tile] = s;   // per-TILE slot: deterministic
    }

    finalize(out);
}

// -------------------- reconstruction CE --------------------
#define REC_THREADS 256
__global__ __launch_bounds__(REC_THREADS)
void rec_kernel(const float* __restrict__ qp, const int* __restrict__ tw,
                float* __restrict__ out) {
    __shared__ float red[REC_THREADS / 32];
    const int tid   = threadIdx.x;
    const int blk   = blockIdx.x;
    const int b     = blk >> 5;
    const int ntile = blk & 31;
    const int n     = ntile * REC_THREADS + tid;

    const float* base = qp + (size_t)b * C_DIM * N_DIM + n;

    float m = -3.4e38f, s = 0.0f;
    #pragma unroll 4
    for (int c = 0; c < C_DIM; c++) {
        float x = base[(size_t)c * N_DIM];
        if (x > m) { s *= __expf(m - x); m = x; }
        s += __expf(x - m);
    }
    int t = tw[(size_t)b * N_DIM + n];
    t = min(max(t, 0), C_DIM - 1);
    float rec = (m + __logf(s)) - base[(size_t)t * N_DIM];

    float ssum = block_sum(rec, red, REC_THREADS / 32);
    if (tid == 0) g_partials[N_TILES + blk] = ssum;

    finalize(out);
}

// -------------------- launch (stream-fork for vq/rec overlap) --------------------
extern "C" void kernel_launch(void* const* d_in, const int* in_sizes, int n_in,
                              void* d_out, int out_size) {
    const float* ze  = (const float*)d_in[0];   // (B,Q,N)
    const float* emb = (const float*)d_in[1];   // (K,Q)
    const float* qp  = (const float*)d_in[2];   // (B,C,N)
    const int*   tw  = (const int*)d_in[3];     // (B,N) int32
    float* out = (float*)d_out;

    static cudaStream_t s1 = nullptr;
    static cudaEvent_t  ef = nullptr, ej = nullptr;
    if (s1 == nullptr) {   // first (non-captured) correctness call only
        cudaStreamCreateWithFlags(&s1, cudaStreamNonBlocking);
        cudaEventCreateWithFlags(&ef, cudaEventDisableTiming);
        cudaEventCreateWithFlags(&ej, cudaEventDisableTiming);
        cudaFuncSetAttribute(vq_gemm, cudaFuncAttributeMaxDynamicSharedMemorySize,
                             SMEM_TOTAL);
    }

    // fork: rec (DRAM-bound, no smem) runs concurrently with vq (tensor-bound)
    cudaEventRecord(ef, 0);
    cudaStreamWaitEvent(s1, ef, 0);
    rec_kernel<<<REC_BLOCKS, REC_THREADS, 0, s1>>>(qp, tw, out);
    vq_gemm<<<VQ_GRID, 128, SMEM_TOTAL>>>(ze, emb, out);
    cudaEventRecord(ej, s1);
    cudaStreamWaitEvent(0, ej, 0);
}

// round 6
// speedup vs baseline: 1.1926x; 1.1926x over previous
#include <cuda_runtime.h>
#include <cuda_bf16.h>
#include <stdint.h>
#include <math.h>

#define B_DIM 8
#define Q_DIM 64
#define N_DIM 8192
#define K_DIM 512
#define C_DIM 256

#define VQ_GRID 296            // persistent vq CTAs (2 per SM)
#define N_TILES 1024           // (B*N)/64 tiles of 64 n-columns
#define REC_BLOCKS 256
#define TOTAL_BLOCKS (VQ_GRID + REC_BLOCKS)   // 552 arrivals
#define NP (N_TILES + REC_BLOCKS)             // 1280 partial slots

__device__ float g_partials[NP];
__device__ int   g_arrived;    // zero-init; reset by the finishing block
__device__ int   g_tile;       // work-stealing cursor; reset by finishing block

// ---------------- smem layout (bytes) ----------------
// rows padded to 144B (= 9 x 16B): conflict-free ldmatrix, 16B-aligned
#define EPAD 144
#define SM_RED   0                     // 32B  (8 floats)
#define SM_Z2    32                    // 1024B (4 partial ze2 sums per column)
#define SM_WMIN  1056                  // 1024B (per-kg per-n mins: [4][64])
#define SM_E2    2080                  // 2048B (||emb_k||^2)
#define SM_ZET   4128                  // 64 * 144 = 9216B  (zeT[n][q] bf16)
#define SM_EMB   13344                 // 512 * 144 = 73728B (emb[k][q] bf16)
#define SMEM_TOTAL 87072

// ---------------- helpers ----------------
__device__ __forceinline__ uint32_t smem_u32(const void* p) {
    uint32_t a;
    asm("{ .reg .u64 t; cvta.to.shared.u64 t, %1; cvt.u32.u64 %0, t; }" : "=r"(a) : "l"(p));
    return a;
}

#define LDSM_X4(r0, r1, r2, r3, addr) \
    asm volatile("ldmatrix.sync.aligned.m8n8.x4.shared.b16 {%0,%1,%2,%3}, [%4];" \
                 : "=r"(r0), "=r"(r1), "=r"(r2), "=r"(r3) : "r"(addr))

#define MMA_BF16(a0, a1, a2, a3, b0, b1, c0, c1, c2, c3) \
    asm volatile("mma.sync.aligned.m16n8k16.row.col.f32.bf16.bf16.f32 " \
                 "{%0,%1,%2,%3}, {%4,%5,%6,%7}, {%8,%9}, {%0,%1,%2,%3};" \
                 : "+f"(c0), "+f"(c1), "+f"(c2), "+f"(c3) \
                 : "r"(a0), "r"(a1), "r"(a2), "r"(a3), "r"(b0), "r"(b1))

__device__ __forceinline__ float block_sum(float v, float* red, int nwarps) {
    #pragma unroll
    for (int off = 16; off > 0; off >>= 1)
        v += __shfl_down_sync(0xFFFFFFFFu, v, off);
    int lane = threadIdx.x & 31;
    int wid  = threadIdx.x >> 5;
    if (lane == 0) red[wid] = v;
    __syncthreads();
    if (wid == 0) {
        v = (lane < nwarps) ? red[lane] : 0.0f;
        #pragma unroll
        for (int off = 16; off > 0; off >>= 1)
            v += __shfl_down_sync(0xFFFFFFFFu, v, off);
    }
    return v;  // valid in thread 0
}

// Last-arriving block (across BOTH kernels) sums all partials in a FIXED
// order (first 128 threads, fixed stride + fixed tree) -> bit-deterministic.
__device__ __forceinline__ void finalize(float* out) {
    __shared__ float fr[4];
    __shared__ int last;
    __threadfence();
    if (threadIdx.x == 0)
        last = (atomicAdd(&g_arrived, 1) == TOTAL_BLOCKS - 1);
    __syncthreads();
    if (!last) return;
    __threadfence();
    float s = 0.0f;
    if (threadIdx.x < 128) {
        for (int i = threadIdx.x; i < NP; i += 128)
            s += g_partials[i];
    }
    #pragma unroll
    for (int off = 16; off > 0; off >>= 1)
        s += __shfl_down_sync(0xFFFFFFFFu, s, off);
    if (threadIdx.x < 128 && (threadIdx.x & 31) == 0)
        fr[threadIdx.x >> 5] = s;
    __syncthreads();
    if (threadIdx.x == 0) {
        out[0] = ((fr[0] + fr[1]) + (fr[2] + fr[3]));
        g_arrived = 0;   // reset for next graph replay
        g_tile = 0;
    }
}

// -------------------- VQ: emb prep + distance GEMM (HMMA bf16) --------------------
// 256 threads = 8 warps: warp = (ng = wid&1  -> n-rows [32*ng, 32*ng+32),
//                                kg = wid>>1 -> codewords [128*kg, 128*kg+128))
__global__ __launch_bounds__(256, 2) void vq_gemm(const float* __restrict__ ze,
                                                  const float* __restrict__ emb,
                                                  float* __restrict__ out) {
    extern __shared__ char smem[];
    __shared__ int tile_sh;
    const uint32_t sb = smem_u32(smem);
    const int tid  = threadIdx.x;
    const int lane = tid & 31;
    const int wid  = tid >> 5;
    const int ng   = wid & 1;
    const int kg   = wid >> 1;

    float* red  = (float*)(smem + SM_RED);
    float* z2s  = (float*)(smem + SM_Z2);
    float* wmin = (float*)(smem + SM_WMIN);

    // ---- one-time: emb fp32 (gmem/L2) -> bf16 padded smem + ||emb||^2 ----
    {
        float* e2 = (float*)(smem + SM_E2);
        #pragma unroll
        for (int i = 0; i < K_DIM / 256; i++) {
            int k = tid + 256 * i;                     // stride-256 rows
            const float4* src = (const float4*)(emb + (size_t)k * Q_DIM);
            char* dst = smem + SM_EMB + k * EPAD;
            float s = 0.0f;
            #pragma unroll
            for (int j = 0; j < 16; j++) {
                float4 v = src[j];
                s = fmaf(v.x, v.x, s); s = fmaf(v.y, v.y, s);
                s = fmaf(v.z, v.z, s); s = fmaf(v.w, v.w, s);
                __nv_bfloat162 p0 = __floats2bfloat162_rn(v.x, v.y);
                __nv_bfloat162 p1 = __floats2bfloat162_rn(v.z, v.w);
                uint2 u;
                u.x = *(uint32_t*)&p0;
                u.y = *(uint32_t*)&p1;
                *(uint2*)(dst + j * 8) = u;
            }
            e2[k] = s;
        }
    }

    const float* e2s = (const float*)(smem + SM_E2);

    for (;;) {
        if (tid == 0) tile_sh = atomicAdd(&g_tile, 1);
        __syncthreads();                 // tile_sh ready + smem reuse guard
        const int tile = tile_sh;
        if (tile >= N_TILES) break;

        const int b  = tile >> 7;
        const int n0 = (tile & 127) << 6;
        const float* zp = ze + (size_t)b * Q_DIM * N_DIM + n0;

        // ---- load ze tile -> zeT[n][q] bf16 + exact fp32 ze2 partials ----
        {
            const int c  = tid & 63;    // column n within tile
            const int qg = tid >> 6;    // q quarter (0..3)
            float z2 = 0.0f;
            #pragma unroll
            for (int i = 0; i < 16; i++) {
                int q = 16 * qg + i;
                float v = zp[(size_t)q * N_DIM + c];
                z2 = fmaf(v, v, z2);
                *(__nv_bfloat16*)(smem + SM_ZET + c * EPAD + q * 2) = __float2bfloat16_rn(v);
            }
            z2s[qg * 64 + c] = z2;
        }
        __syncthreads();

        // ---- A fragments: 2 sets of 16 n-rows, all 4 k-steps ----
        uint32_t a[2][4][4];
        #pragma unroll
        for (int s = 0; s < 2; s++) {
            uint32_t abase = sb + SM_ZET
                           + (uint32_t)(32 * ng + 16 * s + (lane & 15)) * EPAD
                           + (uint32_t)(lane >> 4) * 16u;
            #pragma unroll
            for (int ks = 0; ks < 4; ks++)
                LDSM_X4(a[s][ks][0], a[s][ks][1], a[s][ks][2], a[s][ks][3],
                        abase + ks * 32u);
        }

        float vmin[2][2];
        vmin[0][0] = vmin[0][1] = vmin[1][0] = vmin[1][1] = 3.4e38f;

        const uint32_t bbase = sb + SM_EMB
                             + (uint32_t)(kg * 128 + (lane & 7)) * EPAD
                             + (uint32_t)(lane >> 3) * 16u;

        #pragma unroll 2
        for (int ct = 0; ct < 16; ct++) {     // 8 codewords per iteration
            uint32_t bb[8];
            LDSM_X4(bb[0], bb[1], bb[2], bb[3], bbase + (uint32_t)ct * (8u * EPAD));
            LDSM_X4(bb[4], bb[5], bb[6], bb[7], bbase + (uint32_t)ct * (8u * EPAD) + 64u);

            float2 e2 = *(const float2*)(e2s + kg * 128 + ct * 8 + 2 * (lane & 3));
            #pragma unroll
            for (int s = 0; s < 2; s++) {     // two independent MMA chains
                float c0 = 0.f, c1 = 0.f, c2 = 0.f, c3 = 0.f;
                MMA_BF16(a[s][0][0], a[s][0][1], a[s][0][2], a[s][0][3], bb[0], bb[1], c0, c1, c2, c3);
                MMA_BF16(a[s][1][0], a[s][1][1], a[s][1][2], a[s][1][3], bb[2], bb[3], c0, c1, c2, c3);
                MMA_BF16(a[s][2][0], a[s][2][1], a[s][2][2], a[s][2][3], bb[4], bb[5], c0, c1, c2, c3);
                MMA_BF16(a[s][3][0], a[s][3][1], a[s][3][2], a[s][3][3], bb[6], bb[7], c0, c1, c2, c3);
                vmin[s][0] = fminf(vmin[s][0],
                                   fminf(fmaf(-2.0f, c0, e2.x), fmaf(-2.0f, c1, e2.y)));
                vmin[s][1] = fminf(vmin[s][1],
                                   fminf(fmaf(-2.0f, c2, e2.x), fmaf(-2.0f, c3, e2.y)));
            }
        }

        // min across the 4 lanes of each row-quad (codeword cols)
        #pragma unroll
        for (int s = 0; s < 2; s++) {
            #pragma unroll
            for (int h = 0; h < 2; h++) {
                vmin[s][h] = fminf(vmin[s][h], __shfl_xor_sync(0xFFFFFFFFu, vmin[s][h], 1));
                vmin[s][h] = fminf(vmin[s][h], __shfl_xor_sync(0xFFFFFFFFu, vmin[s][h], 2));
            }
        }
        // qualifying lanes write this warp's 32 per-n mins into wmin[kg][n]
        if ((lane & 3) == 0) {
            int r = lane >> 2;                    // 0..7
            int nb = 32 * ng + r;
            wmin[kg * 64 + nb]      = vmin[0][0];
            wmin[kg * 64 + nb + 8]  = vmin[0][1];
            wmin[kg * 64 + nb + 16] = vmin[1][0];
            wmin[kg * 64 + nb + 24] = vmin[1][1];
        }
        __syncthreads();

        float part = 0.0f;
        if (tid < 64) {
            float m = fminf(fminf(wmin[tid], wmin[64 + tid]),
                            fminf(wmin[128 + tid], wmin[192 + tid]));
            float ze2 = (z2s[tid] + z2s[64 + tid]) + (z2s[128 + tid] + z2s[192 + tid]);
            part = 1.25f * (m + ze2);
        }
        float s = block_sum(part, red, 8);
        if (tid == 0) g_partials[tile] = s;   // per-TILE slot: deterministic
    }

    finalize(out);
}

// -------------------- reconstruction CE --------------------
#define REC_THREADS 256
__global__ __launch_bounds__(REC_THREADS)
void rec_kernel(const float* __restrict__ qp, const int* __restrict__ tw,
                float* __restrict__ out) {
    __shared__ float red[REC_THREADS / 32];
    const int tid   = threadIdx.x;
    const int blk   = blockIdx.x;
    const int b     = blk >> 5;
    const int ntile = blk & 31;
    const int n     = ntile * REC_THREADS + tid;

    const float* base = qp + (size_t)b * C_DIM * N_DIM + n;

    float m = -3.4e38f, s = 0.0f;
    #pragma unroll 4
    for (int c = 0; c < C_DIM; c++) {
        float x = base[(size_t)c * N_DIM];
        if (x > m) { s *= __expf(m - x); m = x; }
        s += __expf(x - m);
    }
    int t = tw[(size_t)b * N_DIM + n];
    t = min(max(t, 0), C_DIM - 1);
    float rec = (m + __logf(s)) - base[(size_t)t * N_DIM];

    float ssum = block_sum(rec, red, REC_THREADS / 32);
    if (tid == 0) g_partials[N_TILES + blk] = ssum;

    finalize(out);
}

// -------------------- launch (stream-fork for vq/rec overlap) --------------------
extern "C" void kernel_launch(void* const* d_in, const int* in_sizes, int n_in,
                              void* d_out, int out_size) {
    const float* ze  = (const float*)d_in[0];   // (B,Q,N)
    const float* emb = (const float*)d_in[1];   // (K,Q)
    const float* qp  = (const float*)d_in[2];   // (B,C,N)
    const int*   tw  = (const int*)d_in[3];     // (B,N) int32
    float* out = (float*)d_out;

    static cudaStream_t s1 = nullptr;
    static cudaEvent_t  ef = nullptr, ej = nullptr;
    if (s1 == nullptr) {   // first (non-captured) correctness call only
        cudaStreamCreateWithFlags(&s1, cudaStreamNonBlocking);
        cudaEventCreateWithFlags(&ef, cudaEventDisableTiming);
        cudaEventCreateWithFlags(&ej, cudaEventDisableTiming);
        cudaFuncSetAttribute(vq_gemm, cudaFuncAttributeMaxDynamicSharedMemorySize,
                             SMEM_TOTAL);
    }

    // fork: rec (DRAM-bound, no smem) runs concurrently with vq (tensor-bound)
    cudaEventRecord(ef, 0);
    cudaStreamWaitEvent(s1, ef, 0);
    rec_kernel<<<REC_BLOCKS, REC_THREADS, 0, s1>>>(qp, tw, out);
    vq_gemm<<<VQ_GRID, 256, SMEM_TOTAL>>>(ze, emb, out);
    cudaEventRecord(ej, s1);
    cudaStreamWaitEvent(0, ej, 0);
}